// round 16
// baseline (speedup 1.0000x reference)
#include <cuda_runtime.h>
#include <cuda_bf16.h>
#include <cstdint>

// B=8, L=4096, D=1024, ALPHA=64. Rows R = 32768.
// out = mask * ( softmax(x @ M + bias) @ C_V^T ),  M = W_Q^T C_K / 32, bias = b_Q C_K / 32
// computed as: out = mask * ( cmean + (A - 1/64) @ C_V^T )
//
// Main kernel: barrier-free, no smem. x via LDG.128 (k-permuted mma slots),
// EXPLICITLY batched 8-wide to force memory-level parallelism. uint2 frag
// tables in mma B-fragment order, L1-hot, batched 8-wide per k-step.
// GEMM2 n-permuted pairwise so the epilogue writes STG.128.

// ---------------- device scratch ----------------
__device__ float g_Mpart[32 * 64 * 1024];    // [sl][a][d] fp32 partials (8 MB)
__device__ float g_biaspart[32 * 64];
__device__ uint2 g_Mfrag[64 * 8 * 32];       // [ki][nt][lane], k-slots {4t..4t+3}
__device__ uint2 g_CVfrag[16 * 4 * 8 * 32];  // [nc][kt][nt][lane], n-permuted pairwise
__device__ float g_cmean[1024];
__device__ float g_bias[64];

// ---------------- helpers ----------------
__device__ __forceinline__ uint32_t f2bf2(float lo, float hi) {
    uint32_t r;
    asm("cvt.rn.bf16x2.f32 %0, %1, %2;" : "=r"(r) : "f"(hi), "f"(lo));
    return r;
}
__device__ __forceinline__ void mma16816(float* c, uint32_t a0, uint32_t a1,
                                         uint32_t a2, uint32_t a3,
                                         uint32_t b0, uint32_t b1) {
    asm volatile(
        "mma.sync.aligned.m16n8k16.row.col.f32.bf16.bf16.f32 "
        "{%0,%1,%2,%3},{%4,%5,%6,%7},{%8,%9},{%0,%1,%2,%3};"
        : "+f"(c[0]), "+f"(c[1]), "+f"(c[2]), "+f"(c[3])
        : "r"(a0), "r"(a1), "r"(a2), "r"(a3), "r"(b0), "r"(b1));
}
__device__ __forceinline__ void cp16(void* d, const void* s) {
    uint32_t a = (uint32_t)__cvta_generic_to_shared(d);
    asm volatile("cp.async.cg.shared.global [%0], [%1], 16;" :: "r"(a), "l"(s));
}
#define CP_COMMIT  asm volatile("cp.async.commit_group;" ::: "memory")
#define CP_WAIT0   asm volatile("cp.async.wait_group 0;" ::: "memory")

// ========== prep1: grid 256 = 8 d-tiles(128) x 32 e-slices(32); 8a x 4d per thread ==========
// smem: Ck [32][64] 8 KB + Wq [32][128] 16 KB + bq [32]
#define P1_SMEM (8192 + 16384 + 128)
__global__ void __launch_bounds__(256, 3)
prep1_kernel(const float* __restrict__ W_Q, const float* __restrict__ C_K,
             const float* __restrict__ b_Q) {
    extern __shared__ float p1s[];
    float* Ck_s = p1s;            // [32][64]
    float* Wq_s = p1s + 2048;     // [32][128]
    float* bq_s = p1s + 2048 + 4096;

    const int tid = threadIdx.x;
    const int bd = blockIdx.x & 7, sl = blockIdx.x >> 3;   // sl 0..31
    const int d0 = bd * 128, e0 = sl * 32;

#pragma unroll
    for (int i = 0; i < 2; i++) {             // C_K: 32 rows x 64
        int idx = tid + i * 256;
        int row = idx >> 4, c = (idx & 15) << 2;
        cp16(&Ck_s[row * 64 + c], &C_K[(size_t)(e0 + row) * 64 + c]);
    }
#pragma unroll
    for (int i = 0; i < 4; i++) {             // W_Q: 32 rows x 128
        int idx = tid + i * 256;
        int row = idx >> 5, c = (idx & 31) << 2;
        cp16(&Wq_s[row * 128 + c], &W_Q[(size_t)(e0 + row) * 1024 + d0 + c]);
    }
    if (tid < 32) bq_s[tid] = b_Q[e0 + tid];
    CP_COMMIT; CP_WAIT0;
    __syncthreads();

    const int aq = (tid & 7) * 8;             // 8 a's
    const int dq = (tid >> 3) * 4;            // 4 d's
    float acc[8][4] = {};
#pragma unroll 4
    for (int e = 0; e < 32; e++) {
        float4 c0 = *(const float4*)&Ck_s[e * 64 + aq];
        float4 c1 = *(const float4*)&Ck_s[e * 64 + aq + 4];
        float4 wv = *(const float4*)&Wq_s[e * 128 + dq];
        float ca[8] = {c0.x, c0.y, c0.z, c0.w, c1.x, c1.y, c1.z, c1.w};
        float wa[4] = {wv.x, wv.y, wv.z, wv.w};
#pragma unroll
        for (int ai = 0; ai < 8; ai++)
#pragma unroll
            for (int dj = 0; dj < 4; dj++) acc[ai][dj] += ca[ai] * wa[dj];
    }
#pragma unroll
    for (int ai = 0; ai < 8; ai++) {
        *(float4*)&g_Mpart[((size_t)sl * 64 + aq + ai) * 1024 + d0 + dq] =
            make_float4(acc[ai][0], acc[ai][1], acc[ai][2], acc[ai][3]);
    }
    if (bd == 0 && tid < 64) {
        float s = 0.f;
#pragma unroll 8
        for (int e = 0; e < 32; e++) s += bq_s[e] * Ck_s[e * 64 + tid];
        g_biaspart[sl * 64 + tid] = s;
    }
}

// ========== prep2: Mfrag reduce + bias | CVfrag pack (n-permuted) + cmean ==========
// grid 128 x 256 = 32768 threads
__global__ void prep2_kernel(const float* __restrict__ C_V) {
    const int id = blockIdx.x * 256 + threadIdx.x;
    if (id < 16384) {
        // Mfrag: lane tig supplies k-slots {4t..4t+3} (matches contiguous x float4)
        const int ki = id >> 8, nt = (id >> 5) & 7, lane = id & 31;
        const int rg = lane >> 2, tig = lane & 3;
        const int n = nt * 8 + rg;
        const int k4 = ki * 16 + 4 * tig;
        float4 m = make_float4(0.f, 0.f, 0.f, 0.f);
#pragma unroll 4
        for (int sl = 0; sl < 32; sl++) {
            float4 p = *(const float4*)(g_Mpart + ((size_t)sl * 64 + n) * 1024 + k4);
            m.x += p.x; m.y += p.y; m.z += p.z; m.w += p.w;
        }
        uint2 v;
        v.x = f2bf2(m.x * 0.03125f, m.y * 0.03125f);
        v.y = f2bf2(m.z * 0.03125f, m.w * 0.03125f);
        g_Mfrag[id] = v;
        if (id < 64) {
            float s = 0.f;
#pragma unroll
            for (int sl = 0; sl < 32; sl++) s += g_biaspart[sl * 64 + id];
            g_bias[id] = s * 0.03125f;
        }
    } else {
        // CVfrag: n-permuted pairwise so GEMM2 epilogue stores float4.
        // block nt = 2*pb + b; slot rg -> logical col pb*16 + 4*(rg>>1) + 2*b + (rg&1)
        const int f = id - 16384;
        const int lane = f & 31, nt = (f >> 5) & 7, kt = (f >> 8) & 3, nc = f >> 10;
        const int rg = lane >> 2, tig = lane & 3;
        const int pb = nt >> 1, b = nt & 1;
        const int n = nc * 64 + pb * 16 + ((rg >> 1) << 2) + 2 * b + (rg & 1);
        const int k2 = kt * 16 + 2 * tig;
        const float* r = C_V + (size_t)n * 64;
        uint2 v;
        v.x = f2bf2(r[k2],     r[k2 + 1]);
        v.y = f2bf2(r[k2 + 8], r[k2 + 9]);
        g_CVfrag[f] = v;
        if (f < 1024) {
            float s2 = 0.f;
            const float* cr = C_V + (size_t)f * 64;
#pragma unroll 8
            for (int j = 0; j < 64; j++) s2 += cr[j];
            g_cmean[f] = s2 * (1.0f / 64.0f);
        }
    }
}

// ========== main: 256 CTAs x 256 thr, 128 rows/CTA, barrier-free, batched MLP ==========
__global__ void __launch_bounds__(256, 2)
col_main(const float* __restrict__ x, const int* __restrict__ mask,
         float* __restrict__ out) {
    const int tid = threadIdx.x;
    const int w = tid >> 5, lane = tid & 31;
    const int rg = lane >> 2, tig = lane & 3;
    const int r0 = blockIdx.x * 128 + w * 16 + rg;
    const float m0 = (mask[r0] != 0) ? 1.0f : 0.0f;
    const float m1 = (mask[r0 + 8] != 0) ? 1.0f : 0.0f;

    // -------- GEMM1: logits = x @ M. 8 LDG.128 batched per kb-block --------
    const float* xr0 = x + (size_t)r0 * 1024 + 4 * tig;
    const float* xr1 = xr0 + (size_t)8 * 1024;
    const uint2* mf = g_Mfrag + lane;

    float acc[8][4];
#pragma unroll
    for (int nt = 0; nt < 8; nt++)
        acc[nt][0] = acc[nt][1] = acc[nt][2] = acc[nt][3] = 0.f;

#pragma unroll 1
    for (int kb = 0; kb < 16; kb++) {
        // batch: 8 independent LDG.128 issued back-to-back (forces MLP=8)
        float4 qa[4], qb[4];
#pragma unroll
        for (int j = 0; j < 4; j++) {
            qa[j] = __ldcs((const float4*)(xr0 + (kb * 4 + j) * 16));
            qb[j] = __ldcs((const float4*)(xr1 + (kb * 4 + j) * 16));
        }
#pragma unroll
        for (int j = 0; j < 4; j++) {
            const int ki = kb * 4 + j;
            // batch the 8 L1-hot frag loads before the mma burst
            uint2 bb[8];
#pragma unroll
            for (int nt = 0; nt < 8; nt++) bb[nt] = mf[(ki * 8 + nt) << 5];
            uint32_t a0 = f2bf2(qa[j].x, qa[j].y), a2 = f2bf2(qa[j].z, qa[j].w);
            uint32_t a1 = f2bf2(qb[j].x, qb[j].y), a3 = f2bf2(qb[j].z, qb[j].w);
#pragma unroll
            for (int nt = 0; nt < 8; nt++)
                mma16816(acc[nt], a0, a1, a2, a3, bb[nt].x, bb[nt].y);
        }
    }

    // -------- softmax, fully in registers --------
#pragma unroll
    for (int nt = 0; nt < 8; nt++) {
        float2 bv = *(const float2*)&g_bias[nt * 8 + 2 * tig];
        acc[nt][0] += bv.x; acc[nt][1] += bv.y; acc[nt][2] += bv.x; acc[nt][3] += bv.y;
    }
    float mx0 = -1e30f, mx1 = -1e30f;
#pragma unroll
    for (int nt = 0; nt < 8; nt++) {
        mx0 = fmaxf(mx0, fmaxf(acc[nt][0], acc[nt][1]));
        mx1 = fmaxf(mx1, fmaxf(acc[nt][2], acc[nt][3]));
    }
    mx0 = fmaxf(mx0, __shfl_xor_sync(0xffffffffu, mx0, 1));
    mx0 = fmaxf(mx0, __shfl_xor_sync(0xffffffffu, mx0, 2));
    mx1 = fmaxf(mx1, __shfl_xor_sync(0xffffffffu, mx1, 1));
    mx1 = fmaxf(mx1, __shfl_xor_sync(0xffffffffu, mx1, 2));
    float s0 = 0.f, s1 = 0.f;
#pragma unroll
    for (int nt = 0; nt < 8; nt++) {
        acc[nt][0] = __expf(acc[nt][0] - mx0); s0 += acc[nt][0];
        acc[nt][1] = __expf(acc[nt][1] - mx0); s0 += acc[nt][1];
        acc[nt][2] = __expf(acc[nt][2] - mx1); s1 += acc[nt][2];
        acc[nt][3] = __expf(acc[nt][3] - mx1); s1 += acc[nt][3];
    }
    s0 += __shfl_xor_sync(0xffffffffu, s0, 1);
    s0 += __shfl_xor_sync(0xffffffffu, s0, 2);
    s1 += __shfl_xor_sync(0xffffffffu, s1, 1);
    s1 += __shfl_xor_sync(0xffffffffu, s1, 2);
    const float i0 = 1.0f / s0, i1 = 1.0f / s1, cC = 1.0f / 64.0f;

    // GEMM1 C-layout == GEMM2 A-fragment layout (standard slots): pack directly
    uint32_t af[4][4];
#pragma unroll
    for (int kt = 0; kt < 4; kt++) {
        af[kt][0] = f2bf2(acc[2 * kt][0] * i0 - cC,     acc[2 * kt][1] * i0 - cC);
        af[kt][1] = f2bf2(acc[2 * kt][2] * i1 - cC,     acc[2 * kt][3] * i1 - cC);
        af[kt][2] = f2bf2(acc[2 * kt + 1][0] * i0 - cC, acc[2 * kt + 1][1] * i0 - cC);
        af[kt][3] = f2bf2(acc[2 * kt + 1][2] * i1 - cC, acc[2 * kt + 1][3] * i1 - cC);
    }

    // -------- GEMM2: out = Acent @ C_V^T, 16 chunks of 64 cols, STG.128 epilogue --------
    const uint2* cvf = g_CVfrag + lane;
    float* out0 = out + (size_t)r0 * 1024 + 4 * tig;
    float* out1 = out0 + (size_t)8 * 1024;

#pragma unroll 1
    for (int nc = 0; nc < 16; nc++) {
        float a2c[8][4];
#pragma unroll
        for (int nt = 0; nt < 8; nt++)
            a2c[nt][0] = a2c[nt][1] = a2c[nt][2] = a2c[nt][3] = 0.f;
#pragma unroll
        for (int kt = 0; kt < 4; kt++) {
            uint2 bb[8];
#pragma unroll
            for (int nt = 0; nt < 8; nt++)
                bb[nt] = cvf[((((nc << 2) + kt) << 3) + nt) << 5];
#pragma unroll
            for (int nt = 0; nt < 8; nt++)
                mma16816(a2c[nt], af[kt][0], af[kt][1], af[kt][2], af[kt][3], bb[nt].x, bb[nt].y);
        }
        // n-permutation: pair (2pb, 2pb+1) -> thread cols pb*16 + 4*tig + {0..3}
#pragma unroll
        for (int pb = 0; pb < 4; pb++) {
            int col = nc * 64 + pb * 16;          // + 4*tig folded into out0/out1
            float4 cm = *(const float4*)(g_cmean + col + 4 * tig);
            __stcs((float4*)(out0 + col),
                   make_float4(m0 * (a2c[2*pb][0]   + cm.x), m0 * (a2c[2*pb][1]   + cm.y),
                               m0 * (a2c[2*pb+1][0] + cm.z), m0 * (a2c[2*pb+1][1] + cm.w)));
            __stcs((float4*)(out1 + col),
                   make_float4(m1 * (a2c[2*pb][2]   + cm.x), m1 * (a2c[2*pb][3]   + cm.y),
                               m1 * (a2c[2*pb+1][2] + cm.z), m1 * (a2c[2*pb+1][3] + cm.w)));
        }
    }
}

// ---------------- launch ----------------
extern "C" void kernel_launch(void* const* d_in, const int* in_sizes, int n_in,
                              void* d_out, int out_size) {
    const float* x    = (const float*)d_in[0];
    const int*   mask = (const int*)d_in[1];
    const float* W_Q  = (const float*)d_in[2];
    const float* b_Q  = (const float*)d_in[3];
    const float* C_K  = (const float*)d_in[4];
    const float* C_V  = (const float*)d_in[5];
    float*       out  = (float*)d_out;

    cudaFuncSetAttribute(prep1_kernel, cudaFuncAttributeMaxDynamicSharedMemorySize, P1_SMEM);

    prep1_kernel<<<256, 256, P1_SMEM>>>(W_Q, C_K, b_Q);
    prep2_kernel<<<128, 256>>>(C_V);
    col_main<<<256, 256>>>(x, mask, out);
}